// round 10
// baseline (speedup 1.0000x reference)
#include <cuda_runtime.h>
#include <cuda_bf16.h>
#include <cstdint>

// ---------------------------------------------------------------------------
// Problem constants
// ---------------------------------------------------------------------------
#define T_STEPS   512
#define IN_DIM    1024
#define DGRID     256
#define OUT_DIM   128
#define NPIX      (DGRID * DGRID)          // 65536
#define KTOT      (2 * NPIX)               // 131072  (interleaved V,S per pixel)

// GEMM tiling / split-K (persistent, dynamic)
#define BM        128
#define BN        128
#define BK        32
#define GSLICE    2048
#define KITERS    (GSLICE / BK)            // 64
// slices 0..63  : merged Ahi*(Whi then Wlo) over KTOT
// slices 64..95 : Alo_v*Whi_v over NPIX
#define NSLICE_T  96
#define NITEMS    384                      // 4 mt * 96 slices
#define GEMM_CTAS 148

// ---------------------------------------------------------------------------
// Device scratch (static allocations only)
// ---------------------------------------------------------------------------
__device__ int            g_perm[IN_DIM];
__device__ float          g_wval[IN_DIM];
__device__ float          g_tanhu[T_STEPS * IN_DIM];
// tagged S words: [parity][row][chunk] = (tag<<32) | ballot(32 px)
__device__ unsigned long long g_S64[2][DGRID][8];
__device__ unsigned       g_ctr;                               // work-item counter
__device__ unsigned       g_A32[(size_t)T_STEPS * NPIX];       // bf16x2 (V,S) 134MB
__device__ unsigned short g_Alo16[(size_t)T_STEPS * NPIX];     // bf16 V-lo    67MB
__device__ __nv_bfloat16  g_Whi_int[(size_t)OUT_DIM * KTOT];   // [o][pix][ch] 33MB
__device__ __nv_bfloat16  g_Wlo_int[(size_t)OUT_DIM * KTOT];   // 33MB
__device__ __nv_bfloat16  g_Whi_v[(size_t)OUT_DIM * NPIX];     // V-only hi   16MB
__device__ float          g_part[(size_t)NSLICE_T * T_STEPS * OUT_DIM]; // 25MB

// ---------------------------------------------------------------------------
// PTX helpers (plain sm_70/80+ features -> safe for .target sm_103)
// ---------------------------------------------------------------------------
__device__ __forceinline__ uint32_t smem_u32(const void* p) {
    return (uint32_t)__cvta_generic_to_shared(p);
}
__device__ __forceinline__ void cp_async16(uint32_t saddr, const void* gaddr) {
    asm volatile("cp.async.cg.shared.global [%0], [%1], 16;" :: "r"(saddr), "l"(gaddr));
}
__device__ __forceinline__ void cp_commit() {
    asm volatile("cp.async.commit_group;" ::: "memory");
}
__device__ __forceinline__ void cp_wait1() {
    asm volatile("cp.async.wait_group 1;" ::: "memory");
}
__device__ __forceinline__ void cp_wait0() {
    asm volatile("cp.async.wait_group 0;" ::: "memory");
}
__device__ __forceinline__ void ldsm_x4(uint32_t& r0, uint32_t& r1, uint32_t& r2,
                                        uint32_t& r3, uint32_t addr) {
    asm volatile("ldmatrix.sync.aligned.m8n8.x4.shared.b16 {%0,%1,%2,%3}, [%4];"
                 : "=r"(r0), "=r"(r1), "=r"(r2), "=r"(r3) : "r"(addr));
}
__device__ __forceinline__ void mma_bf16(float* d, const uint32_t* a, const uint32_t* b) {
    asm volatile(
        "mma.sync.aligned.m16n8k16.row.col.f32.bf16.bf16.f32 "
        "{%0,%1,%2,%3}, {%4,%5,%6,%7}, {%8,%9}, {%0,%1,%2,%3};"
        : "+f"(d[0]), "+f"(d[1]), "+f"(d[2]), "+f"(d[3])
        : "r"(a[0]), "r"(a[1]), "r"(a[2]), "r"(a[3]), "r"(b[0]), "r"(b[1]));
}
// GPU-scope relaxed atomics (NOT volatile/SYS-scope)
__device__ __forceinline__ unsigned long long ld_relaxed_u64(const unsigned long long* p) {
    unsigned long long v;
    asm volatile("ld.relaxed.gpu.global.u64 %0, [%1];" : "=l"(v) : "l"(p) : "memory");
    return v;
}
__device__ __forceinline__ void st_relaxed_u64(unsigned long long* p, unsigned long long v) {
    asm volatile("st.relaxed.gpu.global.u64 [%0], %1;" :: "l"(p), "l"(v) : "memory");
}
__device__ __forceinline__ unsigned short bf2u(__nv_bfloat16 h) {
    return ((__nv_bfloat16_raw)h).x;
}

// ---------------------------------------------------------------------------
// Kernel 0: reset sync state (every graph replay)
// ---------------------------------------------------------------------------
__global__ void init_kernel() {
    int i = blockIdx.x * blockDim.x + threadIdx.x;
    if (i == 0) g_ctr = 0u;
    if (i < 2 * DGRID * 8) ((unsigned long long*)g_S64)[i] = 0ull;
}

// ---------------------------------------------------------------------------
// Kernel 1: discover permutation from the permuted-identity embed matrix
// ---------------------------------------------------------------------------
__global__ void perm_kernel(const float* __restrict__ We) {
    int row = blockIdx.x;
    for (int j = threadIdx.x; j < IN_DIM; j += blockDim.x) {
        float w = We[row * IN_DIM + j];
        if (fabsf(w) > 0.5f) { g_perm[row] = j; g_wval[row] = w; }
    }
}

// ---------------------------------------------------------------------------
// Kernel 2: tanhu[t, ci] = tanh(mask_coarse[ci] * X[t, perm[ci]])
// ---------------------------------------------------------------------------
__global__ void tanhu_kernel(const float* __restrict__ X,
                             const float* __restrict__ mc) {
    int idx = blockIdx.x * blockDim.x + threadIdx.x;
    if (idx >= T_STEPS * IN_DIM) return;
    int t  = idx >> 10;
    int ci = idx & 1023;
    float v = X[(t << 10) + g_perm[ci]] * g_wval[ci];
    g_tanhu[idx] = tanhf(__fmul_rn(mc[ci], v));
}

// ---------------------------------------------------------------------------
// Kernel 3: persistent reservoir scan.  64 blocks x 1024 threads; block b
// owns rows 4b..4b+3 (1 thread/pixel).  The +-8-row halo now spans only
// blocks b+-1, b+-2 -> per-step wait is max over 4 neighbors (was 8).
// Sync protocol identical to R7/R9: tagged 8-byte word per (row, chunk),
// GPU-scope relaxed atomics, one __syncthreads per step.
// ---------------------------------------------------------------------------
__global__ void __launch_bounds__(1024, 1)
scan_kernel(const float* __restrict__ mask_fine) {
    const int b    = blockIdx.x;         // 0..63
    const int tid  = threadIdx.x;        // 0..1023
    const int dy   = tid >> 8;           // 0..3
    const int x    = tid & 255;
    const int y    = (b << 2) + dy;
    const int ci   = ((y >> 3) << 5) + (x >> 3);
    const float mf = mask_fine[(y << 8) + x];
    const int w    = tid >> 5;           // warp 0..31
    const int lane = tid & 31;

    __shared__ unsigned sS[2][20][8];    // [parity][halo row k][chunk]

    const int b5 = (x - 2) & 255, w5 = b5 >> 5, o5 = b5 & 31, w5b = (w5 + 1) & 7;
    const int b9 = (x - 8) & 255, w9 = b9 >> 5, o9 = b9 & 31, w9b = (w9 + 1) & 7;
    const int krow = 8 + dy;             // own row in smem (8..11)

    // halo rows: k=0..7 -> rows 4b-8..4b-1 (warps 0..7);
    //            k=12..19 -> rows 4b+4..4b+11 (warps 8..15)
    int hk = 0, hrow = 0;
    if (w < 8)       { hk = w;     hrow = ((b << 2) - 8 + w) & 255; }
    else if (w < 16) { hk = w + 4; hrow = ((b << 2) - 4 + w) & 255; }
    unsigned long long* hp0 = &g_S64[0][hrow][lane & 7];
    unsigned long long* hp1 = &g_S64[1][hrow][lane & 7];

    // prefill own rows of smem buffer 0 with S(-1)=0
    if (lane == 0) sS[0][8 + (w >> 3)][w & 7] = 0u;

    float V = 0.0f;
    const int pix = (y << 8) + x;

    for (int t = 0; t < T_STEPS; ++t) {
        float u  = __fmul_rn(mf, __ldg(&g_tanhu[(t << 10) + ci]));
        float Vd = __fadd_rn(__fmul_rn(0.9f, V), __fmul_rn(0.5f, u));

        const int sb = t & 1;
        // halo: poll tagged word (tag>=t) and stage payload
        if (w < 16 && lane < 8) {
            unsigned long long* p = (t & 1) ? hp0 : hp1;   // parity (t-1)&1
            unsigned long long v = ld_relaxed_u64(p);
            while ((unsigned)(v >> 32) < (unsigned)t) v = ld_relaxed_u64(p);
            sS[sb][hk][lane] = (unsigned)v;
        }
        __syncthreads();   // the ONLY barrier per step

        int n5 = 0;
#pragma unroll
        for (int d = -2; d <= 2; ++d) {
            unsigned v = __funnelshift_r(sS[sb][krow + d][w5], sS[sb][krow + d][w5b], o5);
            n5 += __popc(v & 0x1Fu);
        }
        int n9 = 0;
#pragma unroll
        for (int d = -8; d <= 8; d += 2) {
            unsigned v = __funnelshift_r(sS[sb][krow + d][w9], sS[sb][krow + d][w9b], o9);
            n9 += __popc(v & 0x15555u);
        }
        float c5  = __fmul_rn((float)n5, 1.0f / 25.0f);
        float c9  = __fmul_rn((float)n9, 1.0f / 81.0f);
        float lat = __fadd_rn(c5, __fmul_rn(-0.5f, c9));

        float Vn = Vd;
        if (Vd >= 0.1f)
            Vn = __fadd_rn(__fadd_rn(Vd, __fmul_rn(0.5f, u)), lat);
        Vn = fminf(Vn, 1.0f);
        bool Sb = (Vn > 0.75f);
        if (Sb) Vn = 0.0f;
        V = Vn;

        // publish: warp w = word (w&7) of own row (4b + (w>>3))
        unsigned ball = __ballot_sync(0xffffffffu, Sb);
        if (lane == 0) {
            unsigned long long pk =
                ((unsigned long long)(unsigned)(t + 1) << 32) | (unsigned long long)ball;
            st_relaxed_u64(&g_S64[t & 1][y][w & 7], pk);
            sS[sb ^ 1][8 + dy][w & 7] = ball;   // own rows for next step
        }

        // stream outputs: ONE 4B evict-first store (V-hi, S) + 2B V-lo store
        __nv_bfloat16 vh = __float2bfloat16(Vn);
        unsigned wrd = (unsigned)bf2u(vh) | ((unsigned)(Sb ? 0x3F80u : 0u) << 16);
        size_t obase = (size_t)t * NPIX + pix;
        __stcs((int*)&g_A32[obase], (int)wrd);
        g_Alo16[obase] = bf2u(__float2bfloat16(Vn - __bfloat162float(vh)));
    }
}

// ---------------------------------------------------------------------------
// Kernel 2b: split W into bf16 hi/lo, interleaved [o][pix][ch] to match A
// layout, plus V-only hi for slice group 2.
// ---------------------------------------------------------------------------
__global__ void wsplit_kernel(const float* __restrict__ W) {
    int idx = blockIdx.x * blockDim.x + threadIdx.x;     // 4 pixels each
    if (idx >= OUT_DIM * NPIX / 4) return;
    int o  = idx / (NPIX / 4);
    int p4 = (idx % (NPIX / 4)) * 4;
    const float* Wv = W + (size_t)o * KTOT + p4;          // V channel
    const float* Ws = Wv + NPIX;                          // S channel
    float4 v = *(const float4*)Wv;
    float4 s = *(const float4*)Ws;
    float vf[4] = {v.x, v.y, v.z, v.w};
    float sf[4] = {s.x, s.y, s.z, s.w};
    unsigned hi[4], lo[4];
    unsigned short hv[4];
#pragma unroll
    for (int i = 0; i < 4; ++i) {
        __nv_bfloat16 vh = __float2bfloat16(vf[i]);
        __nv_bfloat16 vl = __float2bfloat16(vf[i] - __bfloat162float(vh));
        __nv_bfloat16 sh = __float2bfloat16(sf[i]);
        __nv_bfloat16 sl = __float2bfloat16(sf[i] - __bfloat162float(sh));
        hi[i] = (unsigned)bf2u(vh) | ((unsigned)bf2u(sh) << 16);
        lo[i] = (unsigned)bf2u(vl) | ((unsigned)bf2u(sl) << 16);
        hv[i] = bf2u(vh);
    }
    size_t base = (size_t)o * NPIX + p4;                  // uint32 index into _int
    *(uint4*)((unsigned*)g_Whi_int + base) = make_uint4(hi[0], hi[1], hi[2], hi[3]);
    *(uint4*)((unsigned*)g_Wlo_int + base) = make_uint4(lo[0], lo[1], lo[2], lo[3]);
    *(uint2*)&g_Whi_v[base] = *(uint2*)hv;
}

// ---------------------------------------------------------------------------
// Kernel 4: PERSISTENT dynamically-scheduled bf16 HMMA split-K GEMM.
// 148 CTAs, work items claimed via atomicAdd.  Items 0..255: merged slices
// (Ahi x Whi then Ahi x Wlo over the SAME A slice, one accumulator — the
// second A pass is L2-resident).  Items 256..383: Alo_v x Whi_v slices.
// ---------------------------------------------------------------------------
__global__ void __launch_bounds__(256)
mma_gemm_kernel() {
    __shared__ __nv_bfloat16 sA[2][BM][BK + 8];
    __shared__ __nv_bfloat16 sB[2][BN][BK + 8];
    __shared__ int s_item;

    const int tid  = threadIdx.x;
    const int wid  = tid >> 5;
    const int lane = tid & 31;
    const int wm   = wid >> 1;
    const int wn   = wid & 1;
    const int lrow = tid >> 1;
    const int lch  = (tid & 1) << 1;

    const uint32_t sA0 = smem_u32(&sA[0][0][0]);
    const uint32_t sB0 = smem_u32(&sB[0][0][0]);
    const uint32_t bufBytes = (uint32_t)BM * (BK + 8) * 2;
    const uint32_t rowOff = ((uint32_t)lrow * (BK + 8) + lch * 8) * 2;

    const int aRow = wm * 32 + (lane & 15);
    const int aK   = (lane >> 4) << 3;
    const int bRow = wn * 64 + (lane & 7) + ((lane >> 4) << 3);
    const int bK   = ((lane >> 3) & 1) << 3;

    for (;;) {
        __syncthreads();                       // smem + s_item reuse guard
        if (tid == 0) s_item = (int)atomicAdd(&g_ctr, 1u);
        __syncthreads();
        const int item = s_item;
        if (item >= NITEMS) break;

        const int mt = item & 3;
        const int s  = item >> 2;              // slice 0..95
        const __nv_bfloat16 *gA0, *gBh, *gBl;
        int NIT;
        if (s < 64) {                          // merged hi/lo over KTOT
            const size_t k0 = (size_t)s * GSLICE;
            gA0 = (const __nv_bfloat16*)g_A32 + (size_t)(mt * BM + lrow) * KTOT + k0 + lch * 8;
            gBh = g_Whi_int + (size_t)lrow * KTOT + k0 + lch * 8;
            gBl = g_Wlo_int + (size_t)lrow * KTOT + k0 + lch * 8;
            NIT = 2 * KITERS;
        } else {                               // V-lo correction over NPIX
            const size_t k0 = (size_t)(s - 64) * GSLICE;
            gA0 = (const __nv_bfloat16*)g_Alo16 + (size_t)(mt * BM + lrow) * NPIX + k0 + lch * 8;
            gBh = g_Whi_v + (size_t)lrow * NPIX + k0 + lch * 8;
            gBl = gBh;
            NIT = KITERS;
        }

        float d[2][8][4];
#pragma unroll
        for (int mi = 0; mi < 2; ++mi)
#pragma unroll
            for (int ni = 0; ni < 8; ++ni)
#pragma unroll
                for (int r = 0; r < 4; ++r) d[mi][ni][r] = 0.0f;

        cp_async16(sA0 + rowOff, gA0);
        cp_async16(sA0 + rowOff + 16, gA0 + 8);
        cp_async16(sB0 + rowOff, gBh);
        cp_async16(sB0 + rowOff + 16, gBh + 8);
        cp_commit();

        for (int it = 0; it < NIT; ++it) {
            const int cb = it & 1;
            if (it + 1 < NIT) {
                const int nb = (it + 1) & 1;
                const int kidx = (it + 1) & (KITERS - 1);
                const __nv_bfloat16* ga = gA0 + (size_t)kidx * BK;
                const __nv_bfloat16* gb = ((it + 1) < KITERS ? gBh : gBl) + (size_t)kidx * BK;
                cp_async16(sA0 + nb * bufBytes + rowOff, ga);
                cp_async16(sA0 + nb * bufBytes + rowOff + 16, ga + 8);
                cp_async16(sB0 + nb * bufBytes + rowOff, gb);
                cp_async16(sB0 + nb * bufBytes + rowOff + 16, gb + 8);
                cp_commit();
                cp_wait1();
            } else {
                cp_wait0();
            }
            __syncthreads();

#pragma unroll
            for (int ks = 0; ks < 2; ++ks) {
                const int kc = ks * 16;
                uint32_t a[2][4], bf[4][4];
#pragma unroll
                for (int mi = 0; mi < 2; ++mi) {
                    uint32_t addr = sA0 + cb * bufBytes +
                        ((uint32_t)(aRow + mi * 16) * (BK + 8) + kc + aK) * 2;
                    ldsm_x4(a[mi][0], a[mi][1], a[mi][2], a[mi][3], addr);
                }
#pragma unroll
                for (int g = 0; g < 4; ++g) {
                    uint32_t addr = sB0 + cb * bufBytes +
                        ((uint32_t)(bRow + g * 16) * (BK + 8) + kc + bK) * 2;
                    ldsm_x4(bf[g][0], bf[g][1], bf[g][2], bf[g][3], addr);
                }
#pragma unroll
                for (int mi = 0; mi < 2; ++mi)
#pragma unroll
                    for (int g = 0; g < 4; ++g) {
                        mma_bf16(d[mi][g * 2 + 0], a[mi], &bf[g][0]);
                        mma_bf16(d[mi][g * 2 + 1], a[mi], &bf[g][2]);
                    }
            }
            __syncthreads();
        }

#pragma unroll
        for (int mi = 0; mi < 2; ++mi) {
            const int m0 = mt * BM + wm * 32 + mi * 16 + (lane >> 2);
#pragma unroll
            for (int ni = 0; ni < 8; ++ni) {
                const int col = wn * 64 + ni * 8 + (lane & 3) * 2;
                float2 v01 = make_float2(d[mi][ni][0], d[mi][ni][1]);
                float2 v23 = make_float2(d[mi][ni][2], d[mi][ni][3]);
                *reinterpret_cast<float2*>(
                    &g_part[((size_t)s * T_STEPS + m0) * OUT_DIM + col]) = v01;
                *reinterpret_cast<float2*>(
                    &g_part[((size_t)s * T_STEPS + m0 + 8) * OUT_DIM + col]) = v23;
            }
        }
    }
}

// ---------------------------------------------------------------------------
// Kernel 5: deterministic split-K reduction + bias
// ---------------------------------------------------------------------------
__global__ void reduce_kernel(const float* __restrict__ b_out,
                              float* __restrict__ out) {
    int i = blockIdx.x * blockDim.x + threadIdx.x;
    if (i >= T_STEPS * OUT_DIM) return;
    int o = i & (OUT_DIM - 1);
    float sum = 0.0f;
#pragma unroll 8
    for (int ks = 0; ks < NSLICE_T; ++ks)
        sum += g_part[(size_t)ks * (T_STEPS * OUT_DIM) + i];
    out[i] = sum + b_out[o];
}

// ---------------------------------------------------------------------------
// Launch: sequential default stream; scan is launch #4 for the profiler.
// ---------------------------------------------------------------------------
extern "C" void kernel_launch(void* const* d_in, const int* in_sizes, int n_in,
                              void* d_out, int out_size) {
    const float* X  = (const float*)d_in[0];   // [512,1024]
    const float* We = (const float*)d_in[1];   // [1024,1024]
    const float* mc = (const float*)d_in[2];   // [1,1,32,32]
    const float* mf = (const float*)d_in[3];   // [1,1,256,256]
    const float* W  = (const float*)d_in[4];   // [128,2,256,256]
    const float* bo = (const float*)d_in[5];   // [128]
    float* out = (float*)d_out;                // [512,128]

    init_kernel<<<16, 256>>>();
    perm_kernel<<<IN_DIM, 256>>>(We);
    tanhu_kernel<<<(T_STEPS * IN_DIM + 255) / 256, 256>>>(X, mc);
    scan_kernel<<<64, 1024>>>(mf);
    wsplit_kernel<<<(OUT_DIM * NPIX / 4 + 255) / 256, 256>>>(W);
    mma_gemm_kernel<<<GEMM_CTAS, 256>>>();
    reduce_kernel<<<(T_STEPS * OUT_DIM + 255) / 256, 256>>>(bo, out);
}

// round 11
// speedup vs baseline: 1.7517x; 1.7517x over previous
#include <cuda_runtime.h>
#include <cuda_bf16.h>
#include <cstdint>

// ---------------------------------------------------------------------------
// Problem constants
// ---------------------------------------------------------------------------
#define T_STEPS   512
#define IN_DIM    1024
#define DGRID     256
#define OUT_DIM   128
#define NPIX      (DGRID * DGRID)          // 65536
#define KTOT      (2 * NPIX)               // 131072  (interleaved V,S per pixel)

// GEMM tiling / split-K (persistent, dynamic)
#define BM        128
#define BN        128
#define BK        64
#define BKP       (BK + 8)                 // padded row: 72 bf16 = 36 words (conflict-free)
#define GSLICE    2048
#define KIT64     (GSLICE / BK)            // 32
// slices 0..63  : merged Ahi*(Whi then Wlo) over KTOT
// slices 64..95 : Alo_v*Whi_v over NPIX
#define NSLICE_T  96
#define NITEMS    384                      // 4 mt * 96 slices
#define GEMM_CTAS 148
#define GEMM_SMEM (2 * 2 * BM * BKP * 2)   // 73728 bytes

// ---------------------------------------------------------------------------
// Device scratch (static allocations only)
// ---------------------------------------------------------------------------
__device__ int            g_perm[IN_DIM];
__device__ float          g_wval[IN_DIM];
__device__ float          g_tanhu[T_STEPS * IN_DIM];
// tagged S words: [parity][row][chunk] = (tag<<32) | ballot(32 px)
__device__ unsigned long long g_S64[2][DGRID][8];
__device__ unsigned       g_ctr;                               // work-item counter
__device__ unsigned       g_A32[(size_t)T_STEPS * NPIX];       // bf16x2 (V,S) 134MB
__device__ unsigned short g_Alo16[(size_t)T_STEPS * NPIX];     // bf16 V-lo    67MB
__device__ __nv_bfloat16  g_Whi_int[(size_t)OUT_DIM * KTOT];   // [o][pix][ch] 33MB
__device__ __nv_bfloat16  g_Wlo_int[(size_t)OUT_DIM * KTOT];   // 33MB
__device__ __nv_bfloat16  g_Whi_v[(size_t)OUT_DIM * NPIX];     // V-only hi   16MB
__device__ float          g_part[(size_t)NSLICE_T * T_STEPS * OUT_DIM]; // 25MB

// ---------------------------------------------------------------------------
// PTX helpers (plain sm_70/80+ features -> safe for .target sm_103)
// ---------------------------------------------------------------------------
__device__ __forceinline__ uint32_t smem_u32(const void* p) {
    return (uint32_t)__cvta_generic_to_shared(p);
}
__device__ __forceinline__ void cp_async16(uint32_t saddr, const void* gaddr) {
    asm volatile("cp.async.cg.shared.global [%0], [%1], 16;" :: "r"(saddr), "l"(gaddr));
}
__device__ __forceinline__ void cp_commit() {
    asm volatile("cp.async.commit_group;" ::: "memory");
}
__device__ __forceinline__ void cp_wait1() {
    asm volatile("cp.async.wait_group 1;" ::: "memory");
}
__device__ __forceinline__ void cp_wait0() {
    asm volatile("cp.async.wait_group 0;" ::: "memory");
}
__device__ __forceinline__ void ldsm_x4(uint32_t& r0, uint32_t& r1, uint32_t& r2,
                                        uint32_t& r3, uint32_t addr) {
    asm volatile("ldmatrix.sync.aligned.m8n8.x4.shared.b16 {%0,%1,%2,%3}, [%4];"
                 : "=r"(r0), "=r"(r1), "=r"(r2), "=r"(r3) : "r"(addr));
}
__device__ __forceinline__ void mma_bf16(float* d, const uint32_t* a, const uint32_t* b) {
    asm volatile(
        "mma.sync.aligned.m16n8k16.row.col.f32.bf16.bf16.f32 "
        "{%0,%1,%2,%3}, {%4,%5,%6,%7}, {%8,%9}, {%0,%1,%2,%3};"
        : "+f"(d[0]), "+f"(d[1]), "+f"(d[2]), "+f"(d[3])
        : "r"(a[0]), "r"(a[1]), "r"(a[2]), "r"(a[3]), "r"(b[0]), "r"(b[1]));
}
// GPU-scope relaxed atomics (NOT volatile/SYS-scope)
__device__ __forceinline__ unsigned long long ld_relaxed_u64(const unsigned long long* p) {
    unsigned long long v;
    asm volatile("ld.relaxed.gpu.global.u64 %0, [%1];" : "=l"(v) : "l"(p) : "memory");
    return v;
}
__device__ __forceinline__ void st_relaxed_u64(unsigned long long* p, unsigned long long v) {
    asm volatile("st.relaxed.gpu.global.u64 [%0], %1;" :: "l"(p), "l"(v) : "memory");
}
__device__ __forceinline__ unsigned short bf2u(__nv_bfloat16 h) {
    return ((__nv_bfloat16_raw)h).x;
}

// ---------------------------------------------------------------------------
// Kernel 0: reset sync state (every graph replay)
// ---------------------------------------------------------------------------
__global__ void init_kernel() {
    int i = blockIdx.x * blockDim.x + threadIdx.x;
    if (i == 0) g_ctr = 0u;
    if (i < 2 * DGRID * 8) ((unsigned long long*)g_S64)[i] = 0ull;
}

// ---------------------------------------------------------------------------
// Kernel 1: discover permutation from the permuted-identity embed matrix
// ---------------------------------------------------------------------------
__global__ void perm_kernel(const float* __restrict__ We) {
    int row = blockIdx.x;
    for (int j = threadIdx.x; j < IN_DIM; j += blockDim.x) {
        float w = We[row * IN_DIM + j];
        if (fabsf(w) > 0.5f) { g_perm[row] = j; g_wval[row] = w; }
    }
}

// ---------------------------------------------------------------------------
// Kernel 2: tanhu[t, ci] = tanh(mask_coarse[ci] * X[t, perm[ci]])
// ---------------------------------------------------------------------------
__global__ void tanhu_kernel(const float* __restrict__ X,
                             const float* __restrict__ mc) {
    int idx = blockIdx.x * blockDim.x + threadIdx.x;
    if (idx >= T_STEPS * IN_DIM) return;
    int t  = idx >> 10;
    int ci = idx & 1023;
    float v = X[(t << 10) + g_perm[ci]] * g_wval[ci];
    g_tanhu[idx] = tanhf(__fmul_rn(mc[ci], v));
}

// ---------------------------------------------------------------------------
// Kernel 3: persistent reservoir scan — EXACT R9 version (measured 688us).
// 128 blocks x 512 threads; block b owns rows 2b, 2b+1; 1 thread/pixel.
// FROZEN: do not touch (R8 prefetch and R10 4-row variants both regressed).
// ---------------------------------------------------------------------------
__global__ void __launch_bounds__(512, 1)
scan_kernel(const float* __restrict__ mask_fine) {
    const int b    = blockIdx.x;
    const int tid  = threadIdx.x;
    const int dy   = tid >> 8;
    const int x    = tid & 255;
    const int y    = (b << 1) + dy;
    const int ci   = ((y >> 3) << 5) + (x >> 3);
    const float mf = mask_fine[(y << 8) + x];
    const int w    = tid >> 5;           // warp 0..15
    const int lane = tid & 31;

    __shared__ unsigned sS[2][18][8];    // [parity][halo row k][chunk]

    const int b5 = (x - 2) & 255, w5 = b5 >> 5, o5 = b5 & 31, w5b = (w5 + 1) & 7;
    const int b9 = (x - 8) & 255, w9 = b9 >> 5, o9 = b9 & 31, w9b = (w9 + 1) & 7;
    const int krow = 8 + dy;

    // halo assignment: warp w<8 -> k=w (rows y0-8..y0-1); w>=8 -> k=w+2 (y0+2..y0+9)
    int hk, hrow;
    if (w < 8) { hk = w;     hrow = ((b << 1) - 8 + w) & 255; }
    else       { hk = w + 2; hrow = ((b << 1) - 6 + w) & 255; }
    unsigned long long* hp0 = &g_S64[0][hrow][lane & 7];
    unsigned long long* hp1 = &g_S64[1][hrow][lane & 7];

    // prefill own rows of smem buffer 0 with S(-1)=0
    if (lane == 0) sS[0][8 + (w >> 3)][w & 7] = 0u;

    float V = 0.0f;
    const int pix = (y << 8) + x;

    for (int t = 0; t < T_STEPS; ++t) {
        float u  = __fmul_rn(mf, __ldg(&g_tanhu[(t << 10) + ci]));
        float Vd = __fadd_rn(__fmul_rn(0.9f, V), __fmul_rn(0.5f, u));

        const int sb = t & 1;
        // halo: poll tagged word (tag>=t) and stage payload; one L2 RT total
        if (lane < 8) {
            unsigned long long* p = (t & 1) ? hp0 : hp1;   // parity (t-1)&1
            unsigned long long v = ld_relaxed_u64(p);
            while ((unsigned)(v >> 32) < (unsigned)t) v = ld_relaxed_u64(p);
            sS[sb][hk][lane] = (unsigned)v;
        }
        __syncthreads();   // the ONLY barrier per step

        int n5 = 0;
#pragma unroll
        for (int d = -2; d <= 2; ++d) {
            unsigned v = __funnelshift_r(sS[sb][krow + d][w5], sS[sb][krow + d][w5b], o5);
            n5 += __popc(v & 0x1Fu);
        }
        int n9 = 0;
#pragma unroll
        for (int d = -8; d <= 8; d += 2) {
            unsigned v = __funnelshift_r(sS[sb][krow + d][w9], sS[sb][krow + d][w9b], o9);
            n9 += __popc(v & 0x15555u);
        }
        float c5  = __fmul_rn((float)n5, 1.0f / 25.0f);
        float c9  = __fmul_rn((float)n9, 1.0f / 81.0f);
        float lat = __fadd_rn(c5, __fmul_rn(-0.5f, c9));

        float Vn = Vd;
        if (Vd >= 0.1f)
            Vn = __fadd_rn(__fadd_rn(Vd, __fmul_rn(0.5f, u)), lat);
        Vn = fminf(Vn, 1.0f);
        bool Sb = (Vn > 0.75f);
        if (Sb) Vn = 0.0f;
        V = Vn;

        // publish: single tagged 8-byte relaxed GPU-scope store
        unsigned ball = __ballot_sync(0xffffffffu, Sb);
        if (lane == 0) {
            unsigned long long pk =
                ((unsigned long long)(unsigned)(t + 1) << 32) | (unsigned long long)ball;
            st_relaxed_u64(&g_S64[t & 1][y][w & 7], pk);
            sS[sb ^ 1][8 + dy][w & 7] = ball;   // own rows for next step
        }

        // stream outputs: ONE 4B evict-first store (V-hi, S) + 2B V-lo store
        __nv_bfloat16 vh = __float2bfloat16(Vn);
        unsigned wrd = (unsigned)bf2u(vh) | ((unsigned)(Sb ? 0x3F80u : 0u) << 16);
        size_t obase = (size_t)t * NPIX + pix;
        __stcs((int*)&g_A32[obase], (int)wrd);
        g_Alo16[obase] = bf2u(__float2bfloat16(Vn - __bfloat162float(vh)));
    }
}

// ---------------------------------------------------------------------------
// Kernel 2b: split W into bf16 hi/lo, interleaved [o][pix][ch] to match A
// layout, plus V-only hi for slice group 2.
// ---------------------------------------------------------------------------
__global__ void wsplit_kernel(const float* __restrict__ W) {
    int idx = blockIdx.x * blockDim.x + threadIdx.x;     // 4 pixels each
    if (idx >= OUT_DIM * NPIX / 4) return;
    int o  = idx / (NPIX / 4);
    int p4 = (idx % (NPIX / 4)) * 4;
    const float* Wv = W + (size_t)o * KTOT + p4;          // V channel
    const float* Ws = Wv + NPIX;                          // S channel
    float4 v = *(const float4*)Wv;
    float4 s = *(const float4*)Ws;
    float vf[4] = {v.x, v.y, v.z, v.w};
    float sf[4] = {s.x, s.y, s.z, s.w};
    unsigned hi[4], lo[4];
    unsigned short hv[4];
#pragma unroll
    for (int i = 0; i < 4; ++i) {
        __nv_bfloat16 vh = __float2bfloat16(vf[i]);
        __nv_bfloat16 vl = __float2bfloat16(vf[i] - __bfloat162float(vh));
        __nv_bfloat16 sh = __float2bfloat16(sf[i]);
        __nv_bfloat16 sl = __float2bfloat16(sf[i] - __bfloat162float(sh));
        hi[i] = (unsigned)bf2u(vh) | ((unsigned)bf2u(sh) << 16);
        lo[i] = (unsigned)bf2u(vl) | ((unsigned)bf2u(sl) << 16);
        hv[i] = bf2u(vh);
    }
    size_t base = (size_t)o * NPIX + p4;                  // uint32 index into _int
    *(uint4*)((unsigned*)g_Whi_int + base) = make_uint4(hi[0], hi[1], hi[2], hi[3]);
    *(uint4*)((unsigned*)g_Wlo_int + base) = make_uint4(lo[0], lo[1], lo[2], lo[3]);
    *(uint2*)&g_Whi_v[base] = *(uint2*)hv;
}

// ---------------------------------------------------------------------------
// Kernel 4: PERSISTENT dynamically-scheduled bf16 HMMA split-K GEMM, BK=64.
// 148 CTAs; work items via atomicAdd.  Items with s<64: merged slices
// (Ahi x Whi then Ahi x Wlo over the SAME A slice, one accumulator).
// Items s>=64: Alo_v x Whi_v.  Dynamic smem (72KB): [A0|A1|B0|B1] tiles,
// row stride 72 bf16 = 36 words (ldmatrix conflict-free).
// ---------------------------------------------------------------------------
__global__ void __launch_bounds__(256)
mma_gemm_kernel() {
    extern __shared__ __align__(16) unsigned char dynsm[];
    __shared__ int s_item;

    const int tid  = threadIdx.x;
    const int wid  = tid >> 5;
    const int lane = tid & 31;
    const int wm   = wid >> 1;
    const int wn   = wid & 1;
    const int lrow = tid >> 1;           // 0..127
    const int half = tid & 1;            // which 64B half of the 128B row

    const uint32_t tileBytes = (uint32_t)BM * BKP * 2;          // 18432
    const uint32_t sA0 = smem_u32(dynsm);                       // A buf0, A buf1
    const uint32_t sB0 = sA0 + 2 * tileBytes;                   // B buf0, B buf1
    const uint32_t rowOff = ((uint32_t)lrow * BKP + half * 32) * 2;

    const int aRow = wm * 32 + (lane & 15);
    const int aK   = (lane >> 4) << 3;
    const int bRow = wn * 64 + (lane & 7) + ((lane >> 4) << 3);
    const int bK   = ((lane >> 3) & 1) << 3;

    for (;;) {
        __syncthreads();                       // smem + s_item reuse guard
        if (tid == 0) s_item = (int)atomicAdd(&g_ctr, 1u);
        __syncthreads();
        const int item = s_item;
        if (item >= NITEMS) break;

        const int mt = item & 3;
        const int s  = item >> 2;              // slice 0..95
        const __nv_bfloat16 *gA0, *gBh, *gBl;
        int NIT;
        if (s < 64) {                          // merged hi/lo over KTOT
            const size_t k0 = (size_t)s * GSLICE;
            gA0 = (const __nv_bfloat16*)g_A32 + (size_t)(mt * BM + lrow) * KTOT + k0 + half * 32;
            gBh = g_Whi_int + (size_t)lrow * KTOT + k0 + half * 32;
            gBl = g_Wlo_int + (size_t)lrow * KTOT + k0 + half * 32;
            NIT = 2 * KIT64;                   // 64
        } else {                               // V-lo correction over NPIX
            const size_t k0 = (size_t)(s - 64) * GSLICE;
            gA0 = (const __nv_bfloat16*)g_Alo16 + (size_t)(mt * BM + lrow) * NPIX + k0 + half * 32;
            gBh = g_Whi_v + (size_t)lrow * NPIX + k0 + half * 32;
            gBl = gBh;
            NIT = KIT64;                       // 32
        }

        float d[2][8][4];
#pragma unroll
        for (int mi = 0; mi < 2; ++mi)
#pragma unroll
            for (int ni = 0; ni < 8; ++ni)
#pragma unroll
                for (int r = 0; r < 4; ++r) d[mi][ni][r] = 0.0f;

#pragma unroll
        for (int c = 0; c < 4; ++c) {
            cp_async16(sA0 + rowOff + c * 16, gA0 + c * 8);
            cp_async16(sB0 + rowOff + c * 16, gBh + c * 8);
        }
        cp_commit();

        for (int it = 0; it < NIT; ++it) {
            const int cb = it & 1;
            if (it + 1 < NIT) {
                const int nb = (it + 1) & 1;
                const int kidx = (it + 1) & (KIT64 - 1);
                const __nv_bfloat16* ga = gA0 + (size_t)kidx * BK;
                const __nv_bfloat16* gb = ((it + 1) < KIT64 ? gBh : gBl) + (size_t)kidx * BK;
#pragma unroll
                for (int c = 0; c < 4; ++c) {
                    cp_async16(sA0 + nb * tileBytes + rowOff + c * 16, ga + c * 8);
                    cp_async16(sB0 + nb * tileBytes + rowOff + c * 16, gb + c * 8);
                }
                cp_commit();
                cp_wait1();
            } else {
                cp_wait0();
            }
            __syncthreads();

#pragma unroll
            for (int ks = 0; ks < 4; ++ks) {
                const int kc = ks * 16;
                uint32_t a[2][4], bf[4][4];
#pragma unroll
                for (int mi = 0; mi < 2; ++mi) {
                    uint32_t addr = sA0 + cb * tileBytes +
                        ((uint32_t)(aRow + mi * 16) * BKP + kc + aK) * 2;
                    ldsm_x4(a[mi][0], a[mi][1], a[mi][2], a[mi][3], addr);
                }
#pragma unroll
                for (int g = 0; g < 4; ++g) {
                    uint32_t addr = sB0 + cb * tileBytes +
                        ((uint32_t)(bRow + g * 16) * BKP + kc + bK) * 2;
                    ldsm_x4(bf[g][0], bf[g][1], bf[g][2], bf[g][3], addr);
                }
#pragma unroll
                for (int mi = 0; mi < 2; ++mi)
#pragma unroll
                    for (int g = 0; g < 4; ++g) {
                        mma_bf16(d[mi][g * 2 + 0], a[mi], &bf[g][0]);
                        mma_bf16(d[mi][g * 2 + 1], a[mi], &bf[g][2]);
                    }
            }
            __syncthreads();
        }

#pragma unroll
        for (int mi = 0; mi < 2; ++mi) {
            const int m0 = mt * BM + wm * 32 + mi * 16 + (lane >> 2);
#pragma unroll
            for (int ni = 0; ni < 8; ++ni) {
                const int col = wn * 64 + ni * 8 + (lane & 3) * 2;
                float2 v01 = make_float2(d[mi][ni][0], d[mi][ni][1]);
                float2 v23 = make_float2(d[mi][ni][2], d[mi][ni][3]);
                *reinterpret_cast<float2*>(
                    &g_part[((size_t)s * T_STEPS + m0) * OUT_DIM + col]) = v01;
                *reinterpret_cast<float2*>(
                    &g_part[((size_t)s * T_STEPS + m0 + 8) * OUT_DIM + col]) = v23;
            }
        }
    }
}

// ---------------------------------------------------------------------------
// Kernel 5: deterministic split-K reduction + bias
// ---------------------------------------------------------------------------
__global__ void reduce_kernel(const float* __restrict__ b_out,
                              float* __restrict__ out) {
    int i = blockIdx.x * blockDim.x + threadIdx.x;
    if (i >= T_STEPS * OUT_DIM) return;
    int o = i & (OUT_DIM - 1);
    float sum = 0.0f;
#pragma unroll 8
    for (int ks = 0; ks < NSLICE_T; ++ks)
        sum += g_part[(size_t)ks * (T_STEPS * OUT_DIM) + i];
    out[i] = sum + b_out[o];
}

// ---------------------------------------------------------------------------
// Launch: sequential default stream; scan is launch #4 for the profiler.
// ---------------------------------------------------------------------------
extern "C" void kernel_launch(void* const* d_in, const int* in_sizes, int n_in,
                              void* d_out, int out_size) {
    const float* X  = (const float*)d_in[0];   // [512,1024]
    const float* We = (const float*)d_in[1];   // [1024,1024]
    const float* mc = (const float*)d_in[2];   // [1,1,32,32]
    const float* mf = (const float*)d_in[3];   // [1,1,256,256]
    const float* W  = (const float*)d_in[4];   // [128,2,256,256]
    const float* bo = (const float*)d_in[5];   // [128]
    float* out = (float*)d_out;                // [512,128]

    cudaFuncSetAttribute(mma_gemm_kernel,
                         cudaFuncAttributeMaxDynamicSharedMemorySize, GEMM_SMEM);

    init_kernel<<<16, 256>>>();
    perm_kernel<<<IN_DIM, 256>>>(We);
    tanhu_kernel<<<(T_STEPS * IN_DIM + 255) / 256, 256>>>(X, mc);
    scan_kernel<<<128, 512>>>(mf);
    wsplit_kernel<<<(OUT_DIM * NPIX / 4 + 255) / 256, 256>>>(W);
    mma_gemm_kernel<<<GEMM_CTAS, 256, GEMM_SMEM>>>();
    reduce_kernel<<<(T_STEPS * OUT_DIM + 255) / 256, 256>>>(bo, out);
}

// round 12
// speedup vs baseline: 1.8144x; 1.0358x over previous
#include <cuda_runtime.h>
#include <cuda_bf16.h>
#include <cstdint>

// ---------------------------------------------------------------------------
// Problem constants
// ---------------------------------------------------------------------------
#define T_STEPS   512
#define IN_DIM    1024
#define DGRID     256
#define OUT_DIM   128
#define NPIX      (DGRID * DGRID)          // 65536
#define KTOT      (2 * NPIX)               // 131072  (interleaved V,S per pixel)

// GEMM tiling / split-K (persistent, dynamic, R9-measured-best shape)
#define BM        128
#define BN        128
#define BK        32
#define GSLICE    2048
#define KITERS    (GSLICE / BK)            // 64
// slices 0..63 = Ahi*Whi_int, 64..127 = Ahi*Wlo_int, 128..159 = Alo_v*Whi_v
#define NSLICE_T  160
#define NITEMS    (4 * NSLICE_T)           // 640, ordered mt-major
#define GEMM_CTAS 148
#define GEMM_SMEM_DYN 122880               // forces 1 GEMM CTA / SM (2x > 228KB)

// ---------------------------------------------------------------------------
// Device scratch (static allocations only)
// ---------------------------------------------------------------------------
__device__ int            g_perm[IN_DIM];
__device__ float          g_wval[IN_DIM];
__device__ float          g_tanhu[T_STEPS * IN_DIM];
// tagged S words: [parity][row][chunk] = (tag<<32) | ballot(32 px)
__device__ unsigned long long g_S64[2][DGRID][8];
__device__ unsigned       g_ctr;                               // work-item counter
__device__ unsigned       g_sprog[128];                        // per-block scan progress
__device__ unsigned       g_A32[(size_t)T_STEPS * NPIX];       // bf16x2 (V,S) 134MB
__device__ unsigned short g_Alo16[(size_t)T_STEPS * NPIX];     // bf16 V-lo    67MB
__device__ __nv_bfloat16  g_Whi_int[(size_t)OUT_DIM * KTOT];   // [o][pix][ch] 33MB
__device__ __nv_bfloat16  g_Wlo_int[(size_t)OUT_DIM * KTOT];   // 33MB
__device__ __nv_bfloat16  g_Whi_v[(size_t)OUT_DIM * NPIX];     // V-only hi   16MB
__device__ float          g_part[(size_t)NSLICE_T * T_STEPS * OUT_DIM]; // 41MB

// ---------------------------------------------------------------------------
// PTX helpers (plain sm_70/80+ features -> safe for .target sm_103)
// ---------------------------------------------------------------------------
__device__ __forceinline__ uint32_t smem_u32(const void* p) {
    return (uint32_t)__cvta_generic_to_shared(p);
}
__device__ __forceinline__ void cp_async16(uint32_t saddr, const void* gaddr) {
    asm volatile("cp.async.cg.shared.global [%0], [%1], 16;" :: "r"(saddr), "l"(gaddr));
}
__device__ __forceinline__ void cp_commit() {
    asm volatile("cp.async.commit_group;" ::: "memory");
}
__device__ __forceinline__ void cp_wait1() {
    asm volatile("cp.async.wait_group 1;" ::: "memory");
}
__device__ __forceinline__ void cp_wait0() {
    asm volatile("cp.async.wait_group 0;" ::: "memory");
}
__device__ __forceinline__ void ldsm_x4(uint32_t& r0, uint32_t& r1, uint32_t& r2,
                                        uint32_t& r3, uint32_t addr) {
    asm volatile("ldmatrix.sync.aligned.m8n8.x4.shared.b16 {%0,%1,%2,%3}, [%4];"
                 : "=r"(r0), "=r"(r1), "=r"(r2), "=r"(r3) : "r"(addr));
}
__device__ __forceinline__ void mma_bf16(float* d, const uint32_t* a, const uint32_t* b) {
    asm volatile(
        "mma.sync.aligned.m16n8k16.row.col.f32.bf16.bf16.f32 "
        "{%0,%1,%2,%3}, {%4,%5,%6,%7}, {%8,%9}, {%0,%1,%2,%3};"
        : "+f"(d[0]), "+f"(d[1]), "+f"(d[2]), "+f"(d[3])
        : "r"(a[0]), "r"(a[1]), "r"(a[2]), "r"(a[3]), "r"(b[0]), "r"(b[1]));
}
// GPU-scope relaxed atomics (NOT volatile/SYS-scope)
__device__ __forceinline__ unsigned long long ld_relaxed_u64(const unsigned long long* p) {
    unsigned long long v;
    asm volatile("ld.relaxed.gpu.global.u64 %0, [%1];" : "=l"(v) : "l"(p) : "memory");
    return v;
}
__device__ __forceinline__ void st_relaxed_u64(unsigned long long* p, unsigned long long v) {
    asm volatile("st.relaxed.gpu.global.u64 [%0], %1;" :: "l"(p), "l"(v) : "memory");
}
__device__ __forceinline__ unsigned ld_relaxed_u32(const unsigned* p) {
    unsigned v;
    asm volatile("ld.relaxed.gpu.global.u32 %0, [%1];" : "=r"(v) : "l"(p) : "memory");
    return v;
}
__device__ __forceinline__ void st_relaxed_u32(unsigned* p, unsigned v) {
    asm volatile("st.relaxed.gpu.global.u32 [%0], %1;" :: "l"(p), "r"(v) : "memory");
}
__device__ __forceinline__ void fence_acq_gpu() {
    asm volatile("fence.acq_rel.gpu;" ::: "memory");
}
__device__ __forceinline__ void sleep_ns(unsigned n) {
    asm volatile("nanosleep.u32 %0;" :: "r"(n));
}
__device__ __forceinline__ unsigned short bf2u(__nv_bfloat16 h) {
    return ((__nv_bfloat16_raw)h).x;
}

// ---------------------------------------------------------------------------
// Kernel 0: reset sync state (every graph replay)
// ---------------------------------------------------------------------------
__global__ void init_kernel() {
    int i = blockIdx.x * blockDim.x + threadIdx.x;
    if (i == 0) g_ctr = 0u;
    if (i < 128) g_sprog[i] = 0u;
    if (i < 2 * DGRID * 8) ((unsigned long long*)g_S64)[i] = 0ull;
}

// ---------------------------------------------------------------------------
// Kernel 1: discover permutation from the permuted-identity embed matrix
// ---------------------------------------------------------------------------
__global__ void perm_kernel(const float* __restrict__ We) {
    int row = blockIdx.x;
    for (int j = threadIdx.x; j < IN_DIM; j += blockDim.x) {
        float w = We[row * IN_DIM + j];
        if (fabsf(w) > 0.5f) { g_perm[row] = j; g_wval[row] = w; }
    }
}

// ---------------------------------------------------------------------------
// Kernel 2: tanhu[t, ci] = tanh(mask_coarse[ci] * X[t, perm[ci]])
// ---------------------------------------------------------------------------
__global__ void tanhu_kernel(const float* __restrict__ X,
                             const float* __restrict__ mc) {
    int idx = blockIdx.x * blockDim.x + threadIdx.x;
    if (idx >= T_STEPS * IN_DIM) return;
    int t  = idx >> 10;
    int ci = idx & 1023;
    float v = X[(t << 10) + g_perm[ci]] * g_wval[ci];
    g_tanhu[idx] = tanhf(__fmul_rn(mc[ci], v));
}

// ---------------------------------------------------------------------------
// Kernel 3: persistent reservoir scan — R9 FROZEN core (measured 655-688us)
// plus a progress publication every 16 steps: __threadfence by all threads
// (reusing the existing top-of-loop __syncthreads) then tid0 stores
// g_sprog[b]=t, making all A stores of steps < t visible to the gated GEMM.
// ---------------------------------------------------------------------------
__global__ void __launch_bounds__(512, 1)
scan_kernel(const float* __restrict__ mask_fine) {
    const int b    = blockIdx.x;
    const int tid  = threadIdx.x;
    const int dy   = tid >> 8;
    const int x    = tid & 255;
    const int y    = (b << 1) + dy;
    const int ci   = ((y >> 3) << 5) + (x >> 3);
    const float mf = mask_fine[(y << 8) + x];
    const int w    = tid >> 5;           // warp 0..15
    const int lane = tid & 31;

    __shared__ unsigned sS[2][18][8];    // [parity][halo row k][chunk]

    const int b5 = (x - 2) & 255, w5 = b5 >> 5, o5 = b5 & 31, w5b = (w5 + 1) & 7;
    const int b9 = (x - 8) & 255, w9 = b9 >> 5, o9 = b9 & 31, w9b = (w9 + 1) & 7;
    const int krow = 8 + dy;

    // halo assignment: warp w<8 -> k=w (rows y0-8..y0-1); w>=8 -> k=w+2 (y0+2..y0+9)
    int hk, hrow;
    if (w < 8) { hk = w;     hrow = ((b << 1) - 8 + w) & 255; }
    else       { hk = w + 2; hrow = ((b << 1) - 6 + w) & 255; }
    unsigned long long* hp0 = &g_S64[0][hrow][lane & 7];
    unsigned long long* hp1 = &g_S64[1][hrow][lane & 7];

    // prefill own rows of smem buffer 0 with S(-1)=0
    if (lane == 0) sS[0][8 + (w >> 3)][w & 7] = 0u;

    float V = 0.0f;
    const int pix = (y << 8) + x;

    for (int t = 0; t < T_STEPS; ++t) {
        float u  = __fmul_rn(mf, __ldg(&g_tanhu[(t << 10) + ci]));
        float Vd = __fadd_rn(__fmul_rn(0.9f, V), __fmul_rn(0.5f, u));

        const int sb = t & 1;
        // halo: poll tagged word (tag>=t) and stage payload; one L2 RT total
        if (lane < 8) {
            unsigned long long* p = (t & 1) ? hp0 : hp1;   // parity (t-1)&1
            unsigned long long v = ld_relaxed_u64(p);
            while ((unsigned)(v >> 32) < (unsigned)t) v = ld_relaxed_u64(p);
            sS[sb][hk][lane] = (unsigned)v;
        }
        // progress fence every 16 steps (covers A stores of steps < t)
        const bool pub = ((t & 15) == 0) && (t > 0);
        if (pub) __threadfence();
        __syncthreads();   // the ONLY barrier per step
        if (pub && tid == 0) st_relaxed_u32(&g_sprog[b], (unsigned)t);

        int n5 = 0;
#pragma unroll
        for (int d = -2; d <= 2; ++d) {
            unsigned v = __funnelshift_r(sS[sb][krow + d][w5], sS[sb][krow + d][w5b], o5);
            n5 += __popc(v & 0x1Fu);
        }
        int n9 = 0;
#pragma unroll
        for (int d = -8; d <= 8; d += 2) {
            unsigned v = __funnelshift_r(sS[sb][krow + d][w9], sS[sb][krow + d][w9b], o9);
            n9 += __popc(v & 0x15555u);
        }
        float c5  = __fmul_rn((float)n5, 1.0f / 25.0f);
        float c9  = __fmul_rn((float)n9, 1.0f / 81.0f);
        float lat = __fadd_rn(c5, __fmul_rn(-0.5f, c9));

        float Vn = Vd;
        if (Vd >= 0.1f)
            Vn = __fadd_rn(__fadd_rn(Vd, __fmul_rn(0.5f, u)), lat);
        Vn = fminf(Vn, 1.0f);
        bool Sb = (Vn > 0.75f);
        if (Sb) Vn = 0.0f;
        V = Vn;

        // publish: single tagged 8-byte relaxed GPU-scope store
        unsigned ball = __ballot_sync(0xffffffffu, Sb);
        if (lane == 0) {
            unsigned long long pk =
                ((unsigned long long)(unsigned)(t + 1) << 32) | (unsigned long long)ball;
            st_relaxed_u64(&g_S64[t & 1][y][w & 7], pk);
            sS[sb ^ 1][8 + dy][w & 7] = ball;   // own rows for next step
        }

        // stream outputs: ONE 4B evict-first store (V-hi, S) + 2B V-lo store
        __nv_bfloat16 vh = __float2bfloat16(Vn);
        unsigned wrd = (unsigned)bf2u(vh) | ((unsigned)(Sb ? 0x3F80u : 0u) << 16);
        size_t obase = (size_t)t * NPIX + pix;
        __stcs((int*)&g_A32[obase], (int)wrd);
        g_Alo16[obase] = bf2u(__float2bfloat16(Vn - __bfloat162float(vh)));
    }

    // final progress: all 512 steps done and visible
    __threadfence();
    __syncthreads();
    if (tid == 0) st_relaxed_u32(&g_sprog[b], (unsigned)T_STEPS);
}

// ---------------------------------------------------------------------------
// Kernel 2b: split W into bf16 hi/lo, interleaved [o][pix][ch] to match A
// layout, plus V-only hi for slice group 2.  (Side stream, behind init.)
// ---------------------------------------------------------------------------
__global__ void wsplit_kernel(const float* __restrict__ W) {
    int idx = blockIdx.x * blockDim.x + threadIdx.x;     // 4 pixels each
    if (idx >= OUT_DIM * NPIX / 4) return;
    int o  = idx / (NPIX / 4);
    int p4 = (idx % (NPIX / 4)) * 4;
    const float* Wv = W + (size_t)o * KTOT + p4;          // V channel
    const float* Ws = Wv + NPIX;                          // S channel
    float4 v = *(const float4*)Wv;
    float4 s = *(const float4*)Ws;
    float vf[4] = {v.x, v.y, v.z, v.w};
    float sf[4] = {s.x, s.y, s.z, s.w};
    unsigned hi[4], lo[4];
    unsigned short hv[4];
#pragma unroll
    for (int i = 0; i < 4; ++i) {
        __nv_bfloat16 vh = __float2bfloat16(vf[i]);
        __nv_bfloat16 vl = __float2bfloat16(vf[i] - __bfloat162float(vh));
        __nv_bfloat16 sh = __float2bfloat16(sf[i]);
        __nv_bfloat16 sl = __float2bfloat16(sf[i] - __bfloat162float(sh));
        hi[i] = (unsigned)bf2u(vh) | ((unsigned)bf2u(sh) << 16);
        lo[i] = (unsigned)bf2u(vl) | ((unsigned)bf2u(sl) << 16);
        hv[i] = bf2u(vh);
    }
    size_t base = (size_t)o * NPIX + p4;                  // uint32 index into _int
    *(uint4*)((unsigned*)g_Whi_int + base) = make_uint4(hi[0], hi[1], hi[2], hi[3]);
    *(uint4*)((unsigned*)g_Wlo_int + base) = make_uint4(lo[0], lo[1], lo[2], lo[3]);
    *(uint2*)&g_Whi_v[base] = *(uint2*)hv;
}

// ---------------------------------------------------------------------------
// Kernel 4: PERSISTENT gated bf16 HMMA split-K GEMM (R9 inner loop).
// Runs on a side stream CONCURRENTLY with the scan.  Items are mt-major;
// each item waits until min(scan progress) >= (mt+1)*128 before touching A.
// Co-residency engineered: 120KB dynamic smem -> 1 GEMM CTA/SM; regs<=128
// (launch_bounds 256,2) -> a scan CTA always fits beside it (no starvation).
// ---------------------------------------------------------------------------
__global__ void __launch_bounds__(256, 2)
mma_gemm_kernel() {
    extern __shared__ __align__(16) unsigned char dynsm[];
    __shared__ int s_item;

    const int tid  = threadIdx.x;
    const int wid  = tid >> 5;
    const int lane = tid & 31;
    const int wm   = wid >> 1;
    const int wn   = wid & 1;
    const int lrow = tid >> 1;
    const int lch  = (tid & 1) << 1;

    const uint32_t bufBytes = (uint32_t)BM * (BK + 8) * 2;   // 10240
    const uint32_t sA0 = smem_u32(dynsm);                    // A buf0, A buf1
    const uint32_t sB0 = sA0 + 2 * bufBytes;                 // B buf0, B buf1
    const uint32_t rowOff = ((uint32_t)lrow * (BK + 8) + lch * 8) * 2;

    const int aRow = wm * 32 + (lane & 15);
    const int aK   = (lane >> 4) << 3;
    const int bRow = wn * 64 + (lane & 7) + ((lane >> 4) << 3);
    const int bK   = ((lane >> 3) & 1) << 3;

    for (;;) {
        __syncthreads();                       // smem + s_item reuse guard
        if (tid == 0) s_item = (int)atomicAdd(&g_ctr, 1u);
        __syncthreads();
        const int item = s_item;
        if (item >= NITEMS) break;

        const int mt = item / NSLICE_T;        // mt-major: all mt=0 first
        const int s  = item % NSLICE_T;        // slice 0..159

        // gate: wait for scan to finish timesteps [0, (mt+1)*128)
        const unsigned need = (unsigned)((mt + 1) << 7);
        for (;;) {
            int ok = 1;
            if (tid < 128) ok = (ld_relaxed_u32(&g_sprog[tid]) >= need);
            if (__syncthreads_and(ok)) break;
            sleep_ns(2000);
        }
        fence_acq_gpu();

        int seg, slice;
        if (s < 64)       { seg = 0; slice = s; }
        else if (s < 128) { seg = 1; slice = s - 64; }
        else              { seg = 2; slice = s - 128; }
        const size_t k0 = (size_t)slice * GSLICE;

        size_t strideK;
        const __nv_bfloat16 *Abase, *Bbase;
        if (seg == 0)      { strideK = KTOT; Abase = (const __nv_bfloat16*)g_A32;   Bbase = g_Whi_int; }
        else if (seg == 1) { strideK = KTOT; Abase = (const __nv_bfloat16*)g_A32;   Bbase = g_Wlo_int; }
        else               { strideK = NPIX; Abase = (const __nv_bfloat16*)g_Alo16; Bbase = g_Whi_v; }

        const __nv_bfloat16* gA = Abase + (size_t)(mt * BM + lrow) * strideK + k0 + lch * 8;
        const __nv_bfloat16* gB = Bbase + (size_t)lrow * strideK + k0 + lch * 8;

        float d[2][8][4];
#pragma unroll
        for (int mi = 0; mi < 2; ++mi)
#pragma unroll
            for (int ni = 0; ni < 8; ++ni)
#pragma unroll
                for (int r = 0; r < 4; ++r) d[mi][ni][r] = 0.0f;

        cp_async16(sA0 + rowOff, gA);
        cp_async16(sA0 + rowOff + 16, gA + 8);
        cp_async16(sB0 + rowOff, gB);
        cp_async16(sB0 + rowOff + 16, gB + 8);
        cp_commit();

        for (int it = 0; it < KITERS; ++it) {
            const int cb = it & 1;
            if (it + 1 < KITERS) {
                const int nb = (it + 1) & 1;
                const __nv_bfloat16* ga = gA + (size_t)(it + 1) * BK;
                const __nv_bfloat16* gb = gB + (size_t)(it + 1) * BK;
                cp_async16(sA0 + nb * bufBytes + rowOff, ga);
                cp_async16(sA0 + nb * bufBytes + rowOff + 16, ga + 8);
                cp_async16(sB0 + nb * bufBytes + rowOff, gb);
                cp_async16(sB0 + nb * bufBytes + rowOff + 16, gb + 8);
                cp_commit();
                cp_wait1();
            } else {
                cp_wait0();
            }
            __syncthreads();

#pragma unroll
            for (int ks = 0; ks < 2; ++ks) {
                const int kc = ks * 16;
                uint32_t a[2][4], bf[4][4];
#pragma unroll
                for (int mi = 0; mi < 2; ++mi) {
                    uint32_t addr = sA0 + cb * bufBytes +
                        ((uint32_t)(aRow + mi * 16) * (BK + 8) + kc + aK) * 2;
                    ldsm_x4(a[mi][0], a[mi][1], a[mi][2], a[mi][3], addr);
                }
#pragma unroll
                for (int g = 0; g < 4; ++g) {
                    uint32_t addr = sB0 + cb * bufBytes +
                        ((uint32_t)(bRow + g * 16) * (BK + 8) + kc + bK) * 2;
                    ldsm_x4(bf[g][0], bf[g][1], bf[g][2], bf[g][3], addr);
                }
#pragma unroll
                for (int mi = 0; mi < 2; ++mi)
#pragma unroll
                    for (int g = 0; g < 4; ++g) {
                        mma_bf16(d[mi][g * 2 + 0], a[mi], &bf[g][0]);
                        mma_bf16(d[mi][g * 2 + 1], a[mi], &bf[g][2]);
                    }
            }
            __syncthreads();
        }

#pragma unroll
        for (int mi = 0; mi < 2; ++mi) {
            const int m0 = mt * BM + wm * 32 + mi * 16 + (lane >> 2);
#pragma unroll
            for (int ni = 0; ni < 8; ++ni) {
                const int col = wn * 64 + ni * 8 + (lane & 3) * 2;
                float2 v01 = make_float2(d[mi][ni][0], d[mi][ni][1]);
                float2 v23 = make_float2(d[mi][ni][2], d[mi][ni][3]);
                *reinterpret_cast<float2*>(
                    &g_part[((size_t)s * T_STEPS + m0) * OUT_DIM + col]) = v01;
                *reinterpret_cast<float2*>(
                    &g_part[((size_t)s * T_STEPS + m0 + 8) * OUT_DIM + col]) = v23;
            }
        }
    }
}

// ---------------------------------------------------------------------------
// Kernel 5: deterministic split-K reduction + bias
// ---------------------------------------------------------------------------
__global__ void reduce_kernel(const float* __restrict__ b_out,
                              float* __restrict__ out) {
    int i = blockIdx.x * blockDim.x + threadIdx.x;
    if (i >= T_STEPS * OUT_DIM) return;
    int o = i & (OUT_DIM - 1);
    float sum = 0.0f;
#pragma unroll 8
    for (int ks = 0; ks < NSLICE_T; ++ks)
        sum += g_part[(size_t)ks * (T_STEPS * OUT_DIM) + i];
    out[i] = sum + b_out[o];
}

// ---------------------------------------------------------------------------
// Launch: fork/join — scan on main stream, gated persistent GEMM on side
// stream overlapping it.  Scan stays launch #4 on the main stream.
// ---------------------------------------------------------------------------
extern "C" void kernel_launch(void* const* d_in, const int* in_sizes, int n_in,
                              void* d_out, int out_size) {
    const float* X  = (const float*)d_in[0];   // [512,1024]
    const float* We = (const float*)d_in[1];   // [1024,1024]
    const float* mc = (const float*)d_in[2];   // [1,1,32,32]
    const float* mf = (const float*)d_in[3];   // [1,1,256,256]
    const float* W  = (const float*)d_in[4];   // [128,2,256,256]
    const float* bo = (const float*)d_in[5];   // [128]
    float* out = (float*)d_out;                // [512,128]

    cudaFuncSetAttribute(mma_gemm_kernel,
                         cudaFuncAttributeMaxDynamicSharedMemorySize, GEMM_SMEM_DYN);

    cudaStream_t s2;
    cudaStreamCreateWithFlags(&s2, cudaStreamNonBlocking);
    cudaEvent_t eInit, eGemm;
    cudaEventCreateWithFlags(&eInit, cudaEventDisableTiming);
    cudaEventCreateWithFlags(&eGemm, cudaEventDisableTiming);

    // main stream: init, perm, tanhu, scan (launch #4)
    init_kernel<<<16, 256>>>();
    cudaEventRecord(eInit, 0);
    perm_kernel<<<IN_DIM, 256>>>(We);
    tanhu_kernel<<<(T_STEPS * IN_DIM + 255) / 256, 256>>>(X, mc);
    scan_kernel<<<128, 512>>>(mf);

    // side stream: wsplit then gated persistent GEMM (overlaps the scan)
    cudaStreamWaitEvent(s2, eInit, 0);
    wsplit_kernel<<<(OUT_DIM * NPIX / 4 + 255) / 256, 256, 0, s2>>>(W);
    mma_gemm_kernel<<<GEMM_CTAS, 256, GEMM_SMEM_DYN, s2>>>();
    cudaEventRecord(eGemm, s2);

    // join, then reduce
    cudaStreamWaitEvent(0, eGemm, 0);
    reduce_kernel<<<(T_STEPS * OUT_DIM + 255) / 256, 256>>>(bo, out);
}